// round 6
// baseline (speedup 1.0000x reference)
#include <cuda_runtime.h>
#include <math.h>
#include <stdint.h>

#define NB 32
#define NL 128
#define NH 512
#define NG 2048
#define NV 32000
#define NE 128
#define NTOK 4096
#define NVT 250

// ------------------ scratch ------------------
__device__ float g_x0[NTOK * NE];
__device__ float g_gx[2u * NTOK * NG];          // [dir][m][g], m = b*128+t
__device__ float g_bufA[NTOK * 1024];
__device__ float g_bufB[NTOK * 1024];
__device__ float g_hid[NTOK * 128];
__device__ float g_h[2 * NB * NH];
__device__ float g_part[2 * 4 * NG * NB];       // [dir][ks][g][b]
__device__ float g_pmax[(size_t)NTOK * NVT];
__device__ float g_psum[(size_t)NTOK * NVT];
__device__ int   g_parg[(size_t)NTOK * NVT];
__device__ float g_nllw[NTOK];
__device__ float g_wtok[NTOK];
__device__ unsigned int g_barcnt;

// ------------------ helpers ------------------
__device__ __forceinline__ float sigf(float x) {
    return 1.0f / (1.0f + __expf(-x));
}
__device__ __forceinline__ float tanhf_fast(float x) {
    float e = __expf(-2.0f * fabsf(x));
    float r = (1.0f - e) / (1.0f + e);
    return copysignf(r, x);
}

__device__ __forceinline__ void gridbar_inner() {
    __syncthreads();
    if (threadIdx.x == 0) {
        unsigned int t = atomicAdd(&g_barcnt, 1u);
        unsigned int need = ((t >> 7) + 1u) << 7;
        while (*((volatile unsigned int*)&g_barcnt) < need) {
            __nanosleep(32);
        }
    }
    __syncthreads();
}

// packed dual-FMA: acc(lo,hi) += a(lo,hi) * b(lo,hi)
__device__ __forceinline__ void fma2(unsigned long long& acc,
                                     unsigned long long a,
                                     unsigned long long b) {
    asm("fma.rn.f32x2 %0, %1, %2, %0;" : "+l"(acc) : "l"(a), "l"(b));
}
__device__ __forceinline__ float pairsum(unsigned long long p) {
    return __uint_as_float((unsigned)(p & 0xffffffffull)) +
           __uint_as_float((unsigned)(p >> 32));
}

// split fp32 into tf32 hi + tf32 lo (bit patterns stored as float)
__device__ __forceinline__ void tf32split(float x, float& hi, float& lo) {
    unsigned hb;
    asm("cvt.rna.tf32.f32 %0, %1;" : "=r"(hb) : "f"(x));
    float hf = __uint_as_float(hb);
    float l = x - hf;
    unsigned lb;
    asm("cvt.rna.tf32.f32 %0, %1;" : "=r"(lb) : "f"(l));
    hi = hf;
    lo = __uint_as_float(lb);
}

#define MMA_TF32(c, a, b)                                                     \
    asm volatile(                                                             \
        "mma.sync.aligned.m16n8k8.row.col.f32.tf32.tf32.f32 "                 \
        "{%0,%1,%2,%3}, {%4,%5,%6,%7}, {%8,%9}, {%0,%1,%2,%3};"               \
        : "+f"((c)[0]), "+f"((c)[1]), "+f"((c)[2]), "+f"((c)[3])              \
        : "r"((a)[0]), "r"((a)[1]), "r"((a)[2]), "r"((a)[3]),                 \
          "r"((b)[0]), "r"((b)[1]))

// ------------------ embedding ------------------
__global__ __launch_bounds__(256) void k_embed(const int* __restrict__ w,
                                               const float* __restrict__ emb) {
    int i = blockIdx.x * 256 + threadIdx.x;
    g_x0[i] = emb[(size_t)w[i >> 7] * NE + (i & 127)];
}

// ------------------ zero h + barrier ------------------
__global__ __launch_bounds__(256) void k_zero() {
    int i = blockIdx.x * 256 + threadIdx.x;
    if (i < 2 * NB * NH) g_h[i] = 0.0f;
    if (i == 0) g_barcnt = 0u;
}

// ------------------ 3xTF32 tensor-core GEMM (unchanged from R5) ------------------
__global__ __launch_bounds__(256) void k_gemm(const float* __restrict__ A,
                                              const float* __restrict__ W,
                                              const float* __restrict__ bias,
                                              float* __restrict__ C,
                                              int K, int N,
                                              long long wStr, long long bStr,
                                              long long cStr, int relu) {
    int d = blockIdx.z;
    W += (size_t)d * wStr;
    bias += (size_t)d * bStr;
    C += (size_t)d * cStr;

    __shared__ float Ah[128 * 20];
    __shared__ float Al[128 * 20];
    __shared__ float Bh[128 * 20];
    __shared__ float Bl[128 * 20];

    int tid = threadIdx.x;
    int m0 = blockIdx.y << 7, n0 = blockIdx.x << 7;

    int lr = tid >> 2;
    int lkq = (tid & 3) << 2;

    const float* Ap0 = A + (size_t)(m0 + lr) * K + lkq;
    const float* Ap1 = A + (size_t)(m0 + lr + 64) * K + lkq;
    const float* Wp0 = W + (size_t)(n0 + lr) * K + lkq;
    const float* Wp1 = W + (size_t)(n0 + lr + 64) * K + lkq;

    int wid = tid >> 5, lane = tid & 31;
    int gid = lane >> 2, t4 = lane & 3;
    int wm = (wid >> 2) << 6;
    int wn = (wid & 3) << 5;

    float acc[4][4][4];
#pragma unroll
    for (int mt = 0; mt < 4; mt++)
#pragma unroll
        for (int nt = 0; nt < 4; nt++)
#pragma unroll
            for (int r = 0; r < 4; r++) acc[mt][nt][r] = 0.0f;

    for (int kt = 0; kt < K; kt += 16) {
        float4 a0 = *(const float4*)(Ap0 + kt);
        float4 a1 = *(const float4*)(Ap1 + kt);
        float4 w0 = *(const float4*)(Wp0 + kt);
        float4 w1 = *(const float4*)(Wp1 + kt);
        __syncthreads();
        {
            float h, l;
            float* dA0h = &Ah[lr * 20 + lkq];        float* dA0l = &Al[lr * 20 + lkq];
            float* dA1h = &Ah[(lr + 64) * 20 + lkq]; float* dA1l = &Al[(lr + 64) * 20 + lkq];
            float* dB0h = &Bh[lr * 20 + lkq];        float* dB0l = &Bl[lr * 20 + lkq];
            float* dB1h = &Bh[(lr + 64) * 20 + lkq]; float* dB1l = &Bl[(lr + 64) * 20 + lkq];
            tf32split(a0.x, h, l); dA0h[0] = h; dA0l[0] = l;
            tf32split(a0.y, h, l); dA0h[1] = h; dA0l[1] = l;
            tf32split(a0.z, h, l); dA0h[2] = h; dA0l[2] = l;
            tf32split(a0.w, h, l); dA0h[3] = h; dA0l[3] = l;
            tf32split(a1.x, h, l); dA1h[0] = h; dA1l[0] = l;
            tf32split(a1.y, h, l); dA1h[1] = h; dA1l[1] = l;
            tf32split(a1.z, h, l); dA1h[2] = h; dA1l[2] = l;
            tf32split(a1.w, h, l); dA1h[3] = h; dA1l[3] = l;
            tf32split(w0.x, h, l); dB0h[0] = h; dB0l[0] = l;
            tf32split(w0.y, h, l); dB0h[1] = h; dB0l[1] = l;
            tf32split(w0.z, h, l); dB0h[2] = h; dB0l[2] = l;
            tf32split(w0.w, h, l); dB0h[3] = h; dB0l[3] = l;
            tf32split(w1.x, h, l); dB1h[0] = h; dB1l[0] = l;
            tf32split(w1.y, h, l); dB1h[1] = h; dB1l[1] = l;
            tf32split(w1.z, h, l); dB1h[2] = h; dB1l[2] = l;
            tf32split(w1.w, h, l); dB1h[3] = h; dB1l[3] = l;
        }
        __syncthreads();

#pragma unroll
        for (int k8 = 0; k8 < 16; k8 += 8) {
            unsigned ah[4][4], al[4][4];
#pragma unroll
            for (int mt = 0; mt < 4; mt++) {
                int r0i = (wm + (mt << 4) + gid) * 20 + k8 + t4;
                int r1i = (wm + (mt << 4) + gid + 8) * 20 + k8 + t4;
                ah[mt][0] = __float_as_uint(Ah[r0i]);
                ah[mt][1] = __float_as_uint(Ah[r1i]);
                ah[mt][2] = __float_as_uint(Ah[r0i + 4]);
                ah[mt][3] = __float_as_uint(Ah[r1i + 4]);
                al[mt][0] = __float_as_uint(Al[r0i]);
                al[mt][1] = __float_as_uint(Al[r1i]);
                al[mt][2] = __float_as_uint(Al[r0i + 4]);
                al[mt][3] = __float_as_uint(Al[r1i + 4]);
            }
            unsigned bh[4][2], bl[4][2];
#pragma unroll
            for (int nt = 0; nt < 4; nt++) {
                int ci = (wn + (nt << 3) + gid) * 20 + k8 + t4;
                bh[nt][0] = __float_as_uint(Bh[ci]);
                bh[nt][1] = __float_as_uint(Bh[ci + 4]);
                bl[nt][0] = __float_as_uint(Bl[ci]);
                bl[nt][1] = __float_as_uint(Bl[ci + 4]);
            }
#pragma unroll
            for (int mt = 0; mt < 4; mt++)
#pragma unroll
                for (int nt = 0; nt < 4; nt++) {
                    MMA_TF32(acc[mt][nt], ah[mt], bh[nt]);
                    MMA_TF32(acc[mt][nt], ah[mt], bl[nt]);
                    MMA_TF32(acc[mt][nt], al[mt], bh[nt]);
                }
        }
    }

#pragma unroll
    for (int mt = 0; mt < 4; mt++) {
#pragma unroll
        for (int nt = 0; nt < 4; nt++) {
            int m = m0 + wm + (mt << 4) + gid;
            int n = n0 + wn + (nt << 3) + (t4 << 1);
            float bv0 = bias[n], bv1 = bias[n + 1];
            float v0 = acc[mt][nt][0] + bv0;
            float v1 = acc[mt][nt][1] + bv1;
            float v2 = acc[mt][nt][2] + bv0;
            float v3 = acc[mt][nt][3] + bv1;
            if (relu) {
                v0 = fmaxf(v0, 0.0f); v1 = fmaxf(v1, 0.0f);
                v2 = fmaxf(v2, 0.0f); v3 = fmaxf(v3, 0.0f);
            }
            float2 p0 = {v0, v1};
            float2 p1 = {v2, v3};
            *(float2*)(C + (size_t)m * N + n) = p0;
            *(float2*)(C + (size_t)(m + 8) * N + n) = p1;
        }
    }
}

// ------------------ persistent BiLSTM layer scan v3 ------------------
// 128 blocks x 256 threads. GEMM role: block=(dir, ks in 4, gt in 16) computes
// partial gates[128 rows]x[32 b] over k-slice; Whh tile (64KB) resident in smem.
// Combine role: block=(dir, jt in 64), thread owns one (b, j): c,h in registers.
// FFMA2 (f32x2) packed math; 2 grid barriers per step.
__global__ __launch_bounds__(256) void k_scan(const float* __restrict__ gx,
                                              const float* __restrict__ whh,
                                              const float* __restrict__ mask,
                                              float* __restrict__ out) {
    extern __shared__ float sm[];
    float* Ws = sm;                 // [128][132] rows x k-slice
    float* Hs = sm + 128 * 132;     // [32][132]  b x k-slice

    int tid = threadIdx.x;
    int bid = blockIdx.x;
    int d = bid >> 6;
    int ks = (bid >> 4) & 3;
    int gt = bid & 15;
    int g0 = gt << 7;
    int k0 = ks << 7;
    const float* whhd = whh + (size_t)d * NG * NH;

    // preload Whh tile once: 128 rows x 128 k
    {
        int row = tid >> 1;
        int kq = (tid & 1) << 6;
        const float* src = whhd + (size_t)(g0 + row) * NH + k0 + kq;
        float* dst = &Ws[row * 132 + kq];
#pragma unroll
        for (int q = 0; q < 16; q++) {
            *(float4*)(dst + q * 4) = __ldg((const float4*)(src + q * 4));
        }
    }

    // gemm-role thread tile: 4 rows x 4 batches
    int rg = tid >> 3;              // 0..31 -> rows rg*4..rg*4+3
    int bg = tid & 7;               // 0..7  -> b  bg*4..bg*4+3

    // combine role: thread owns (b, j)
    int jt = bid & 63;
    int cb = tid & 31;
    int jq = tid >> 5;              // 0..7
    int cj = (jt << 3) + jq;
    float creg = 0.0f, hreg = 0.0f;

    const float* ghd = g_h + (size_t)d * NB * NH;

    __syncthreads();

    for (int s = 0; s < NL; s++) {
        int t = d ? (NL - 1 - s) : s;

        // ---- stage h slice into smem ----
        {
            int b = tid >> 3;
            int kq = (tid & 7) << 4;
            const float* src = ghd + (size_t)b * NH + k0 + kq;
            float* dst = &Hs[b * 132 + kq];
#pragma unroll
            for (int q = 0; q < 4; q++) {
                float4 v = __ldcg((const float4*)(src + q * 4));
                *(float4*)(dst + q * 4) = v;
            }
        }
        __syncthreads();

        // ---- recurrent GEMM partial (FFMA2) ----
        unsigned long long acc2[4][4];
#pragma unroll
        for (int i = 0; i < 4; i++)
#pragma unroll
            for (int j = 0; j < 4; j++) acc2[i][j] = 0ull;

        const float* wrow0 = &Ws[(rg << 2) * 132];
        const float* hrow0 = &Hs[(bg << 2) * 132];
        for (int kb = 0; kb < 128; kb += 4) {
            unsigned long long hx[4], hy[4];
#pragma unroll
            for (int j = 0; j < 4; j++) {
                ulonglong2 hv = *(const ulonglong2*)(hrow0 + j * 132 + kb);
                hx[j] = hv.x; hy[j] = hv.y;
            }
#pragma unroll
            for (int i = 0; i < 4; i++) {
                ulonglong2 wv = *(const ulonglong2*)(wrow0 + i * 132 + kb);
#pragma unroll
                for (int j = 0; j < 4; j++) {
                    fma2(acc2[i][j], wv.x, hx[j]);
                    fma2(acc2[i][j], wv.y, hy[j]);
                }
            }
        }

        // write partials: g_part[((d*4+ks)*NG + g)*NB + b], float4 over b
        {
            size_t pbase = ((size_t)(d * 4 + ks) * NG + g0) * NB;
#pragma unroll
            for (int i = 0; i < 4; i++) {
                float4 pv = {pairsum(acc2[i][0]), pairsum(acc2[i][1]),
                             pairsum(acc2[i][2]), pairsum(acc2[i][3])};
                *(float4*)&g_part[pbase + (size_t)((rg << 2) + i) * NB + (bg << 2)] = pv;
            }
        }
        __threadfence();
        gridbar_inner();

        // ---- combine: one (b,j) per thread, c/h in registers ----
        {
            float gate[4];
            const float* gxr = gx + ((size_t)d * NTOK + (size_t)cb * NL + t) * NG;
#pragma unroll
            for (int gi = 0; gi < 4; gi++) {
                int g = gi * NH + cj;
                float v = __ldg(&gxr[g]);
#pragma unroll
                for (int kss = 0; kss < 4; kss++)
                    v += __ldcg(&g_part[((size_t)(d * 4 + kss) * NG + g) * NB + cb]);
                gate[gi] = v;
            }
            float cn = sigf(gate[1]) * creg + sigf(gate[0]) * tanhf_fast(gate[2]);
            float hn = sigf(gate[3]) * tanhf_fast(cn);
            float mt = mask[cb * NL + t];
            hreg = hreg + (hn - hreg) * mt;
            creg = creg + (cn - creg) * mt;
            g_h[((size_t)d * NB + cb) * NH + cj] = hreg;
            out[((size_t)cb * NL + t) * 1024 + (d << 9) + cj] = hreg;
        }
        __threadfence();
        gridbar_inner();
    }
}

// ------------------ decoder2: logits tile + online softmax partials ------------------
__global__ __launch_bounds__(256) void k_dec2(const float* __restrict__ w2,
                                              const float* __restrict__ b2) {
    int vt = blockIdx.x;
    int mt = blockIdx.y;
    int v0 = vt << 7, m0 = mt << 6;

    __shared__ float Ash[32 * 68];
    __shared__ float Wsh[32 * 132];
    __shared__ float rmax[1024];
    __shared__ int   rarg[1024];
    __shared__ float smax[64];

    int tid = threadIdx.x;
    int tm = tid >> 4, tn = tid & 15;

    float acc[4][8];
#pragma unroll
    for (int i = 0; i < 4; i++)
#pragma unroll
        for (int j = 0; j < 8; j++) acc[i][j] = 0.0f;

    for (int kc = 0; kc < 4; kc++) {
        int kb = kc << 5;
        __syncthreads();
        {
            int ar = tid >> 2, akq = (tid & 3) << 3;
            const float* ap = g_hid + (size_t)(m0 + ar) * 128 + kb + akq;
            float4 u0 = *(const float4*)ap;
            float4 u1 = *(const float4*)(ap + 4);
            Ash[(akq + 0) * 68 + ar] = u0.x; Ash[(akq + 1) * 68 + ar] = u0.y;
            Ash[(akq + 2) * 68 + ar] = u0.z; Ash[(akq + 3) * 68 + ar] = u0.w;
            Ash[(akq + 4) * 68 + ar] = u1.x; Ash[(akq + 5) * 68 + ar] = u1.y;
            Ash[(akq + 6) * 68 + ar] = u1.z; Ash[(akq + 7) * 68 + ar] = u1.w;

            int wr = tid >> 1, wkq = (tid & 1) << 4;
            const float* wp = w2 + (size_t)(v0 + wr) * 128 + kb + wkq;
            float4 q0 = *(const float4*)wp;
            float4 q1 = *(const float4*)(wp + 4);
            float4 q2 = *(const float4*)(wp + 8);
            float4 q3 = *(const float4*)(wp + 12);
            Wsh[(wkq + 0) * 132 + wr] = q0.x;  Wsh[(wkq + 1) * 132 + wr] = q0.y;
            Wsh[(wkq + 2) * 132 + wr] = q0.z;  Wsh[(wkq + 3) * 132 + wr] = q0.w;
            Wsh[(wkq + 4) * 132 + wr] = q1.x;  Wsh[(wkq + 5) * 132 + wr] = q1.y;
            Wsh[(wkq + 6) * 132 + wr] = q1.z;  Wsh[(wkq + 7) * 132 + wr] = q1.w;
            Wsh[(wkq + 8) * 132 + wr] = q2.x;  Wsh[(wkq + 9) * 132 + wr] = q2.y;
            Wsh[(wkq + 10) * 132 + wr] = q2.z; Wsh[(wkq + 11) * 132 + wr] = q2.w;
            Wsh[(wkq + 12) * 132 + wr] = q3.x; Wsh[(wkq + 13) * 132 + wr] = q3.y;
            Wsh[(wkq + 14) * 132 + wr] = q3.z; Wsh[(wkq + 15) * 132 + wr] = q3.w;
        }
        __syncthreads();
#pragma unroll
        for (int k = 0; k < 32; k++) {
            float4 a = *(const float4*)&Ash[k * 68 + (tm << 2)];
            float4 w0 = *(const float4*)&Wsh[k * 132 + (tn << 3)];
            float4 w1 = *(const float4*)&Wsh[k * 132 + (tn << 3) + 4];
            float av[4] = {a.x, a.y, a.z, a.w};
            float wv[8] = {w0.x, w0.y, w0.z, w0.w, w1.x, w1.y, w1.z, w1.w};
#pragma unroll
            for (int i = 0; i < 4; i++)
#pragma unroll
                for (int j = 0; j < 8; j++) acc[i][j] += av[i] * wv[j];
        }
    }

#pragma unroll
    for (int i = 0; i < 4; i++) {
        int ml = tm * 4 + i;
        float lm = -1e30f;
        int la = 0;
#pragma unroll
        for (int j = 0; j < 8; j++) {
            int v = v0 + (tn << 3) + j;
            float lg = acc[i][j] + b2[v];
            acc[i][j] = lg;
            if (lg > lm) { lm = lg; la = v; }
        }
        rmax[ml * 16 + tn] = lm;
        rarg[ml * 16 + tn] = la;
    }
    __syncthreads();
    if (tid < 64) {
        float bm = -1e30f;
        int ba = 0;
        for (int q = 0; q < 16; q++) {
            float v = rmax[tid * 16 + q];
            if (v > bm) { bm = v; ba = rarg[tid * 16 + q]; }
        }
        smax[tid] = bm;
        g_pmax[(size_t)(m0 + tid) * NVT + vt] = bm;
        g_parg[(size_t)(m0 + tid) * NVT + vt] = ba;
    }
    __syncthreads();
#pragma unroll
    for (int i = 0; i < 4; i++) {
        int ml = tm * 4 + i;
        float s = 0.0f;
        float mx = smax[ml];
#pragma unroll
        for (int j = 0; j < 8; j++) s += __expf(acc[i][j] - mx);
        rmax[ml * 16 + tn] = s;
    }
    __syncthreads();
    if (tid < 64) {
        float s = 0.0f;
        for (int q = 0; q < 16; q++) s += rmax[tid * 16 + q];
        g_psum[(size_t)(m0 + tid) * NVT + vt] = s;
    }
}

// ------------------ per-token combine ------------------
__global__ __launch_bounds__(256) void k_comb(const float* __restrict__ w2,
                                              const float* __restrict__ b2,
                                              const int* __restrict__ tgt,
                                              const float* __restrict__ cew,
                                              float* __restrict__ dout) {
    int warp = threadIdx.x >> 5, lane = threadIdx.x & 31;
    int m = blockIdx.x * 8 + warp;

    float lm = -1e30f, ls = 0.0f;
    int la = 0;
    for (int vt = lane; vt < NVT; vt += 32) {
        float tmx = g_pmax[(size_t)m * NVT + vt];
        float tsm = g_psum[(size_t)m * NVT + vt];
        int tag = g_parg[(size_t)m * NVT + vt];
        if (tmx > lm) {
            ls = ls * __expf(lm - tmx) + tsm;
            lm = tmx;
            la = tag;
        } else {
            ls += tsm * __expf(tmx - lm);
        }
    }
#pragma unroll
    for (int off = 16; off; off >>= 1) {
        float om = __shfl_down_sync(0xffffffffu, lm, off);
        float os = __shfl_down_sync(0xffffffffu, ls, off);
        int oa = __shfl_down_sync(0xffffffffu, la, off);
        float nm = fmaxf(lm, om);
        float ns = ls * __expf(lm - nm) + os * __expf(om - nm);
        int na = (om > lm) ? oa : ((om == lm && oa < la) ? oa : la);
        lm = nm; ls = ns; la = na;
    }

    int tg = tgt[m];
    float4 hv = *(const float4*)&g_hid[(size_t)m * 128 + lane * 4];
    float4 wv = *(const float4*)&w2[(size_t)tg * 128 + lane * 4];
    float dp = hv.x * wv.x + hv.y * wv.y + hv.z * wv.z + hv.w * wv.w;
#pragma unroll
    for (int off = 16; off; off >>= 1) dp += __shfl_down_sync(0xffffffffu, dp, off);

    if (lane == 0) {
        float logit_t = dp + b2[tg];
        float lse = lm + logf(ls);
        float nll = lse - logit_t;
        float w = cew[tg];
        g_nllw[m] = nll * w;
        g_wtok[m] = w;
        dout[1 + m] = (float)la;
    }
}

// ------------------ final loss reduce ------------------
__global__ __launch_bounds__(256) void k_loss(float* __restrict__ dout) {
    __shared__ float s1[256];
    __shared__ float s2[256];
    int tid = threadIdx.x;
    float a = 0.0f, b = 0.0f;
    for (int i = tid; i < NTOK; i += 256) { a += g_nllw[i]; b += g_wtok[i]; }
    s1[tid] = a; s2[tid] = b;
    __syncthreads();
    for (int off = 128; off; off >>= 1) {
        if (tid < off) { s1[tid] += s1[tid + off]; s2[tid] += s2[tid + off]; }
        __syncthreads();
    }
    if (tid == 0) dout[0] = s1[0] / s2[0];
}

// ------------------ launch ------------------
extern "C" void kernel_launch(void* const* d_in, const int* in_sizes, int n_in,
                              void* d_out, int out_size) {
    const int* inp_word = (const int*)d_in[0];
    const float* inp_mask = (const float*)d_in[1];
    const int* tgt_word = (const int*)d_in[3];
    const float* emb = (const float*)d_in[4];
    const float* w_ih0 = (const float*)d_in[5];
    const float* w_hh0 = (const float*)d_in[6];
    const float* b0 = (const float*)d_in[7];
    const float* w_ih = (const float*)d_in[8];
    const float* w_hh = (const float*)d_in[9];
    const float* bb = (const float*)d_in[10];
    const float* dec_w1 = (const float*)d_in[11];
    const float* dec_b1 = (const float*)d_in[12];
    const float* dec_w2 = (const float*)d_in[13];
    const float* dec_b2 = (const float*)d_in[14];
    const float* cew = (const float*)d_in[15];
    float* out = (float*)d_out;

    float *px0, *pgx, *pA, *pB, *phid;
    cudaGetSymbolAddress((void**)&px0, g_x0);
    cudaGetSymbolAddress((void**)&pgx, g_gx);
    cudaGetSymbolAddress((void**)&pA, g_bufA);
    cudaGetSymbolAddress((void**)&pB, g_bufB);
    cudaGetSymbolAddress((void**)&phid, g_hid);

    const int scan_smem = (128 * 132 + 32 * 132) * 4;   // 84480 B
    cudaFuncSetAttribute(k_scan, cudaFuncAttributeMaxDynamicSharedMemorySize, scan_smem);

    // 1. embedding
    k_embed<<<(NTOK * NE) / 256, 256>>>(inp_word, emb);

    // 2. layer 0: gx = x @ Wih0^T + b0 (both dirs)
    k_gemm<<<dim3(NG / 128, NTOK / 128, 2), 256>>>(px0, w_ih0, b0, pgx,
                                                   NE, NG,
                                                   (long long)NG * NE, NG,
                                                   (long long)NTOK * NG, 0);
    k_zero<<<128, 256>>>();
    k_scan<<<128, 256, scan_smem>>>(pgx, w_hh0, inp_mask, pA);

    // 3. layer 1
    k_gemm<<<dim3(NG / 128, NTOK / 128, 2), 256>>>(pA, w_ih, bb, pgx,
                                                   1024, NG,
                                                   (long long)NG * 1024, NG,
                                                   (long long)NTOK * NG, 0);
    k_zero<<<128, 256>>>();
    k_scan<<<128, 256, scan_smem>>>(pgx, w_hh, inp_mask, pB);

    // 4. layer 2
    k_gemm<<<dim3(NG / 128, NTOK / 128, 2), 256>>>(pB, w_ih + (size_t)2 * NG * 1024,
                                                   bb + 2 * NG, pgx,
                                                   1024, NG,
                                                   (long long)NG * 1024, NG,
                                                   (long long)NTOK * NG, 0);
    k_zero<<<128, 256>>>();
    k_scan<<<128, 256, scan_smem>>>(pgx, w_hh + (size_t)2 * NG * NH, inp_mask, pA);

    // 5. decoder layer 1 (relu)
    k_gemm<<<dim3(1, NTOK / 128, 1), 256>>>(pA, dec_w1, dec_b1, phid,
                                            1024, 128, 0, 0, 0, 1);

    // 6. decoder layer 2 + fused online softmax partials
    k_dec2<<<dim3(NVT, NTOK / 64), 256>>>(dec_w2, dec_b2);

    // 7. per-token combine
    k_comb<<<NTOK / 8, 256>>>(dec_w2, dec_b2, tgt_word, cew, out);

    // 8. loss reduce
    k_loss<<<1, 256>>>(out);
}

// round 7
// speedup vs baseline: 1.1396x; 1.1396x over previous
#include <cuda_runtime.h>
#include <math.h>
#include <stdint.h>

#define NB 32
#define NL 128
#define NH 512
#define NG 2048
#define NV 32000
#define NE 128
#define NTOK 4096
#define NVT 250

// weight-plane arena offsets (floats)
#define OFF_WIH0 0
#define OFF_WIH1 524288
#define OFF_WIH2 4718592
#define OFF_W1   8912896
#define OFF_W2   9043968
#define WARENA   13139968

// ------------------ scratch ------------------
__device__ float g_wh[WARENA];
__device__ float g_wl[WARENA];
__device__ float g_ah[NTOK * 1024];
__device__ float g_al[NTOK * 1024];
__device__ float g_gx[2u * NTOK * NG];          // [dir][m][g], m = b*128+t
__device__ float g_bufA[NTOK * 1024];
__device__ float g_bufB[NTOK * 1024];
__device__ float g_hid[NTOK * 128];
__device__ float g_hidh[NTOK * 128];
__device__ float g_hidl[NTOK * 128];
__device__ float g_h[2 * NB * NH];
__device__ float g_c[2 * NB * NH];
__device__ float g_part[2 * 4 * NG * NB];       // [dir][ks][g][b]
__device__ float g_pmax[(size_t)NTOK * NVT];
__device__ float g_psum[(size_t)NTOK * NVT];
__device__ int   g_parg[(size_t)NTOK * NVT];
__device__ float g_nllw[NTOK];
__device__ float g_wtok[NTOK];
__device__ unsigned int g_barcnt;

// ------------------ helpers ------------------
__device__ __forceinline__ float sigf(float x) {
    return 1.0f / (1.0f + __expf(-x));
}
__device__ __forceinline__ float tanhf_fast(float x) {
    float e = __expf(-2.0f * fabsf(x));
    float r = (1.0f - e) / (1.0f + e);
    return copysignf(r, x);
}

__device__ __forceinline__ void gridbar() {
    __syncthreads();
    if (threadIdx.x == 0) {
        __threadfence();
        unsigned int t = atomicAdd(&g_barcnt, 1u);
        unsigned int need = ((t >> 7) + 1u) << 7;
        while (*((volatile unsigned int*)&g_barcnt) < need) {
            __nanosleep(32);
        }
    }
    __syncthreads();
}

__device__ __forceinline__ void tf32split(float x, float& hi, float& lo) {
    unsigned hb;
    asm("cvt.rna.tf32.f32 %0, %1;" : "=r"(hb) : "f"(x));
    float hf = __uint_as_float(hb);
    float l = x - hf;
    unsigned lb;
    asm("cvt.rna.tf32.f32 %0, %1;" : "=r"(lb) : "f"(l));
    hi = hf;
    lo = __uint_as_float(lb);
}

#define MMA_TF32(c, a, b)                                                     \
    asm volatile(                                                             \
        "mma.sync.aligned.m16n8k8.row.col.f32.tf32.tf32.f32 "                 \
        "{%0,%1,%2,%3}, {%4,%5,%6,%7}, {%8,%9}, {%0,%1,%2,%3};"               \
        : "+f"((c)[0]), "+f"((c)[1]), "+f"((c)[2]), "+f"((c)[3])              \
        : "r"((a)[0]), "r"((a)[1]), "r"((a)[2]), "r"((a)[3]),                 \
          "r"((b)[0]), "r"((b)[1]))

__device__ __forceinline__ void cp16(uint32_t dst, const float* src) {
    asm volatile("cp.async.cg.shared.global [%0], [%1], 16;" :: "r"(dst), "l"(src));
}
#define CP_COMMIT() asm volatile("cp.async.commit_group;")
#define CP_WAIT1()  asm volatile("cp.async.wait_group 1;")
#define CP_WAIT0()  asm volatile("cp.async.wait_group 0;")

// stage layout: 4 planes (AH, AL, BH, BL) x 128 rows x 20 floats
#define PLANE 2560
#define STAGE 10240

// ------------------ split kernel ------------------
__global__ __launch_bounds__(256) void k_split(const float* __restrict__ s,
                                               float* __restrict__ dh,
                                               float* __restrict__ dl, int n4) {
    int i = blockIdx.x * 256 + threadIdx.x;
    if (i < n4) {
        float4 v = ((const float4*)s)[i];
        float4 h4, l4;
        tf32split(v.x, h4.x, l4.x);
        tf32split(v.y, h4.y, l4.y);
        tf32split(v.z, h4.z, l4.z);
        tf32split(v.w, h4.w, l4.w);
        ((float4*)dh)[i] = h4;
        ((float4*)dl)[i] = l4;
    }
}

// ------------------ embedding (writes split planes) ------------------
__global__ __launch_bounds__(256) void k_embed(const int* __restrict__ w,
                                               const float* __restrict__ emb) {
    int i = blockIdx.x * 256 + threadIdx.x;
    float v = emb[(size_t)w[i >> 7] * NE + (i & 127)];
    float h, l;
    tf32split(v, h, l);
    g_ah[i] = h;
    g_al[i] = l;
}

// ------------------ zero h/c + barrier ------------------
__global__ __launch_bounds__(256) void k_zero() {
    int i = blockIdx.x * 256 + threadIdx.x;
    if (i < 2 * NB * NH) { g_h[i] = 0.0f; g_c[i] = 0.0f; }
    if (i == 0) g_barcnt = 0u;
}

// ------------------ 3xTF32 mma GEMM, presplit inputs, cp.async pipeline ----
// C[m][n] = act(sum_k A[m][k]*W[n][k] + bias[n]); 128x128 tile, BK=16,
// 256 threads = 8 warps (2m x 4n), warp tile 64x32.
// mode: 0 = store; 2 = relu + store + write g_hidh/g_hidl split planes.
__global__ __launch_bounds__(256) void k_gemm2(const float* __restrict__ Ahp,
                                               const float* __restrict__ Alp,
                                               const float* __restrict__ Whp,
                                               const float* __restrict__ Wlp,
                                               const float* __restrict__ bias,
                                               float* __restrict__ C,
                                               int K, int N,
                                               long long wStr, long long bStr,
                                               long long cStr, int mode) {
    extern __shared__ float smf[];
    uint32_t smb = (uint32_t)__cvta_generic_to_shared(smf);

    int d = blockIdx.z;
    Whp += (size_t)d * wStr;
    Wlp += (size_t)d * wStr;
    bias += (size_t)d * bStr;
    C += (size_t)d * cStr;

    int tid = threadIdx.x;
    int m0 = blockIdx.y << 7, n0 = blockIdx.x << 7;
    int lr = tid >> 2, lkq = (tid & 3) << 2;

    const float* pA0h = Ahp + (size_t)(m0 + lr) * K + lkq;
    const float* pA1h = Ahp + (size_t)(m0 + lr + 64) * K + lkq;
    const float* pA0l = Alp + (size_t)(m0 + lr) * K + lkq;
    const float* pA1l = Alp + (size_t)(m0 + lr + 64) * K + lkq;
    const float* pB0h = Whp + (size_t)(n0 + lr) * K + lkq;
    const float* pB1h = Whp + (size_t)(n0 + lr + 64) * K + lkq;
    const float* pB0l = Wlp + (size_t)(n0 + lr) * K + lkq;
    const float* pB1l = Wlp + (size_t)(n0 + lr + 64) * K + lkq;

    uint32_t o0 = (uint32_t)((0 * PLANE + lr * 20 + lkq) * 4);
    uint32_t o1 = (uint32_t)((0 * PLANE + (lr + 64) * 20 + lkq) * 4);
    uint32_t o2 = (uint32_t)((1 * PLANE + lr * 20 + lkq) * 4);
    uint32_t o3 = (uint32_t)((1 * PLANE + (lr + 64) * 20 + lkq) * 4);
    uint32_t o4 = (uint32_t)((2 * PLANE + lr * 20 + lkq) * 4);
    uint32_t o5 = (uint32_t)((2 * PLANE + (lr + 64) * 20 + lkq) * 4);
    uint32_t o6 = (uint32_t)((3 * PLANE + lr * 20 + lkq) * 4);
    uint32_t o7 = (uint32_t)((3 * PLANE + (lr + 64) * 20 + lkq) * 4);

    int wid = tid >> 5, lane = tid & 31;
    int gid = lane >> 2, t4 = lane & 3;
    int wm = (wid >> 2) << 6;
    int wn = (wid & 3) << 5;

    float acc[4][4][4];
#pragma unroll
    for (int mt = 0; mt < 4; mt++)
#pragma unroll
        for (int nt = 0; nt < 4; nt++)
#pragma unroll
            for (int r = 0; r < 4; r++) acc[mt][nt][r] = 0.0f;

    int T = K >> 4;
    // issue tile 0 into stage 0
    {
        uint32_t b = smb;
        cp16(b + o0, pA0h); cp16(b + o1, pA1h);
        cp16(b + o2, pA0l); cp16(b + o3, pA1l);
        cp16(b + o4, pB0h); cp16(b + o5, pB1h);
        cp16(b + o6, pB0l); cp16(b + o7, pB1l);
        CP_COMMIT();
    }

    for (int kt = 0; kt < T; kt++) {
        int s = kt & 1;
        if (kt + 1 < T) {
            int ko = (kt + 1) << 4;
            uint32_t b = smb + (uint32_t)((s ^ 1) * STAGE * 4);
            cp16(b + o0, pA0h + ko); cp16(b + o1, pA1h + ko);
            cp16(b + o2, pA0l + ko); cp16(b + o3, pA1l + ko);
            cp16(b + o4, pB0h + ko); cp16(b + o5, pB1h + ko);
            cp16(b + o6, pB0l + ko); cp16(b + o7, pB1l + ko);
            CP_COMMIT();
            CP_WAIT1();
        } else {
            CP_WAIT0();
        }
        __syncthreads();
        const float* S = smf + s * STAGE;

#pragma unroll
        for (int k8 = 0; k8 < 16; k8 += 8) {
            unsigned ah[4][4], al[4][4];
#pragma unroll
            for (int mt = 0; mt < 4; mt++) {
                int r0i = (wm + (mt << 4) + gid) * 20 + k8 + t4;
                int r1i = (wm + (mt << 4) + gid + 8) * 20 + k8 + t4;
                ah[mt][0] = __float_as_uint(S[r0i]);
                ah[mt][1] = __float_as_uint(S[r1i]);
                ah[mt][2] = __float_as_uint(S[r0i + 4]);
                ah[mt][3] = __float_as_uint(S[r1i + 4]);
                al[mt][0] = __float_as_uint(S[PLANE + r0i]);
                al[mt][1] = __float_as_uint(S[PLANE + r1i]);
                al[mt][2] = __float_as_uint(S[PLANE + r0i + 4]);
                al[mt][3] = __float_as_uint(S[PLANE + r1i + 4]);
            }
            unsigned bh[4][2], bl[4][2];
#pragma unroll
            for (int nt = 0; nt < 4; nt++) {
                int ci = (wn + (nt << 3) + gid) * 20 + k8 + t4;
                bh[nt][0] = __float_as_uint(S[2 * PLANE + ci]);
                bh[nt][1] = __float_as_uint(S[2 * PLANE + ci + 4]);
                bl[nt][0] = __float_as_uint(S[3 * PLANE + ci]);
                bl[nt][1] = __float_as_uint(S[3 * PLANE + ci + 4]);
            }
#pragma unroll
            for (int mt = 0; mt < 4; mt++)
#pragma unroll
                for (int nt = 0; nt < 4; nt++) {
                    MMA_TF32(acc[mt][nt], ah[mt], bh[nt]);
                    MMA_TF32(acc[mt][nt], ah[mt], bl[nt]);
                    MMA_TF32(acc[mt][nt], al[mt], bh[nt]);
                }
        }
        __syncthreads();
    }

#pragma unroll
    for (int mt = 0; mt < 4; mt++) {
#pragma unroll
        for (int nt = 0; nt < 4; nt++) {
            int m = m0 + wm + (mt << 4) + gid;
            int n = n0 + wn + (nt << 3) + (t4 << 1);
            float bv0 = bias[n], bv1 = bias[n + 1];
            float v0 = acc[mt][nt][0] + bv0;
            float v1 = acc[mt][nt][1] + bv1;
            float v2 = acc[mt][nt][2] + bv0;
            float v3 = acc[mt][nt][3] + bv1;
            if (mode) {
                v0 = fmaxf(v0, 0.0f); v1 = fmaxf(v1, 0.0f);
                v2 = fmaxf(v2, 0.0f); v3 = fmaxf(v3, 0.0f);
            }
            float2 p0 = {v0, v1};
            float2 p1 = {v2, v3};
            *(float2*)(C + (size_t)m * N + n) = p0;
            *(float2*)(C + (size_t)(m + 8) * N + n) = p1;
            if (mode == 2) {
                float h, l;
                size_t i0 = (size_t)m * N + n;
                size_t i1 = (size_t)(m + 8) * N + n;
                tf32split(v0, h, l); g_hidh[i0] = h;     g_hidl[i0] = l;
                tf32split(v1, h, l); g_hidh[i0 + 1] = h; g_hidl[i0 + 1] = l;
                tf32split(v2, h, l); g_hidh[i1] = h;     g_hidl[i1] = l;
                tf32split(v3, h, l); g_hidh[i1 + 1] = h; g_hidl[i1 + 1] = l;
            }
        }
    }
}

// ------------------ decoder2 mma: logits tile + online softmax partials ----
// A = w2 planes (v rows), B = hid planes (token rows), K=128.
// block tile 128 v x 128 tokens; per-token max/argmax/sumexp over the v-tile.
__global__ __launch_bounds__(256) void k_dec2m(const float* __restrict__ b2) {
    extern __shared__ float smf[];
    uint32_t smb = (uint32_t)__cvta_generic_to_shared(smf);
    __shared__ float wmax[256];
    __shared__ int   warg[256];
    __shared__ float wsum[256];
    __shared__ float bmx[128];

    const float* Ahp = g_wh + OFF_W2;
    const float* Alp = g_wl + OFF_W2;

    int tid = threadIdx.x;
    int vt = blockIdx.x;
    int v0 = vt << 7;
    int n0 = blockIdx.y << 7;
    int lr = tid >> 2, lkq = (tid & 3) << 2;
    const int K = 128;

    const float* pA0h = Ahp + (size_t)(v0 + lr) * K + lkq;
    const float* pA1h = Ahp + (size_t)(v0 + lr + 64) * K + lkq;
    const float* pA0l = Alp + (size_t)(v0 + lr) * K + lkq;
    const float* pA1l = Alp + (size_t)(v0 + lr + 64) * K + lkq;
    const float* pB0h = g_hidh + (size_t)(n0 + lr) * K + lkq;
    const float* pB1h = g_hidh + (size_t)(n0 + lr + 64) * K + lkq;
    const float* pB0l = g_hidl + (size_t)(n0 + lr) * K + lkq;
    const float* pB1l = g_hidl + (size_t)(n0 + lr + 64) * K + lkq;

    uint32_t o0 = (uint32_t)((0 * PLANE + lr * 20 + lkq) * 4);
    uint32_t o1 = (uint32_t)((0 * PLANE + (lr + 64) * 20 + lkq) * 4);
    uint32_t o2 = (uint32_t)((1 * PLANE + lr * 20 + lkq) * 4);
    uint32_t o3 = (uint32_t)((1 * PLANE + (lr + 64) * 20 + lkq) * 4);
    uint32_t o4 = (uint32_t)((2 * PLANE + lr * 20 + lkq) * 4);
    uint32_t o5 = (uint32_t)((2 * PLANE + (lr + 64) * 20 + lkq) * 4);
    uint32_t o6 = (uint32_t)((3 * PLANE + lr * 20 + lkq) * 4);
    uint32_t o7 = (uint32_t)((3 * PLANE + (lr + 64) * 20 + lkq) * 4);

    int wid = tid >> 5, lane = tid & 31;
    int gid = lane >> 2, t4 = lane & 3;
    int wm = (wid >> 2) << 6;
    int wn = (wid & 3) << 5;

    float acc[4][4][4];
#pragma unroll
    for (int mt = 0; mt < 4; mt++)
#pragma unroll
        for (int nt = 0; nt < 4; nt++)
#pragma unroll
            for (int r = 0; r < 4; r++) acc[mt][nt][r] = 0.0f;

    const int T = 8;
    {
        uint32_t b = smb;
        cp16(b + o0, pA0h); cp16(b + o1, pA1h);
        cp16(b + o2, pA0l); cp16(b + o3, pA1l);
        cp16(b + o4, pB0h); cp16(b + o5, pB1h);
        cp16(b + o6, pB0l); cp16(b + o7, pB1l);
        CP_COMMIT();
    }
    for (int kt = 0; kt < T; kt++) {
        int s = kt & 1;
        if (kt + 1 < T) {
            int ko = (kt + 1) << 4;
            uint32_t b = smb + (uint32_t)((s ^ 1) * STAGE * 4);
            cp16(b + o0, pA0h + ko); cp16(b + o1, pA1h + ko);
            cp16(b + o2, pA0l + ko); cp16(b + o3, pA1l + ko);
            cp16(b + o4, pB0h + ko); cp16(b + o5, pB1h + ko);
            cp16(b + o6, pB0l + ko); cp16(b + o7, pB1l + ko);
            CP_COMMIT();
            CP_WAIT1();
        } else {
            CP_WAIT0();
        }
        __syncthreads();
        const float* S = smf + s * STAGE;
#pragma unroll
        for (int k8 = 0; k8 < 16; k8 += 8) {
            unsigned ah[4][4], al[4][4];
#pragma unroll
            for (int mt = 0; mt < 4; mt++) {
                int r0i = (wm + (mt << 4) + gid) * 20 + k8 + t4;
                int r1i = (wm + (mt << 4) + gid + 8) * 20 + k8 + t4;
                ah[mt][0] = __float_as_uint(S[r0i]);
                ah[mt][1] = __float_as_uint(S[r1i]);
                ah[mt][2] = __float_as_uint(S[r0i + 4]);
                ah[mt][3] = __float_as_uint(S[r1i + 4]);
                al[mt][0] = __float_as_uint(S[PLANE + r0i]);
                al[mt][1] = __float_as_uint(S[PLANE + r1i]);
                al[mt][2] = __float_as_uint(S[PLANE + r0i + 4]);
                al[mt][3] = __float_as_uint(S[PLANE + r1i + 4]);
            }
            unsigned bh[4][2], bl[4][2];
#pragma unroll
            for (int nt = 0; nt < 4; nt++) {
                int ci = (wn + (nt << 3) + gid) * 20 + k8 + t4;
                bh[nt][0] = __float_as_uint(S[2 * PLANE + ci]);
                bh[nt][1] = __float_as_uint(S[2 * PLANE + ci + 4]);
                bl[nt][0] = __float_as_uint(S[3 * PLANE + ci]);
                bl[nt][1] = __float_as_uint(S[3 * PLANE + ci + 4]);
            }
#pragma unroll
            for (int mt = 0; mt < 4; mt++)
#pragma unroll
                for (int nt = 0; nt < 4; nt++) {
                    MMA_TF32(acc[mt][nt], ah[mt], bh[nt]);
                    MMA_TF32(acc[mt][nt], ah[mt], bl[nt]);
                    MMA_TF32(acc[mt][nt], al[mt], bh[nt]);
                }
        }
        __syncthreads();
    }

    // bias add (rows = v)
    float bvv[4][2];
#pragma unroll
    for (int mt = 0; mt < 4; mt++) {
        bvv[mt][0] = b2[v0 + wm + (mt << 4) + gid];
        bvv[mt][1] = b2[v0 + wm + (mt << 4) + gid + 8];
    }
#pragma unroll
    for (int mt = 0; mt < 4; mt++)
#pragma unroll
        for (int nt = 0; nt < 4; nt++) {
            acc[mt][nt][0] += bvv[mt][0];
            acc[mt][nt][1] += bvv[mt][0];
            acc[mt][nt][2] += bvv[mt][1];
            acc[mt][nt][3] += bvv[mt][1];
        }

    // per-token max/argmax over this v-tile
#pragma unroll
    for (int nt = 0; nt < 4; nt++) {
#pragma unroll
        for (int c = 0; c < 2; c++) {
            float lm = -1e30f;
            int la = 0;
#pragma unroll
            for (int mt = 0; mt < 4; mt++)
#pragma unroll
                for (int ro = 0; ro < 2; ro++) {
                    float lg = acc[mt][nt][ro * 2 + c];
                    if (lg > lm) {
                        lm = lg;
                        la = v0 + wm + (mt << 4) + gid + ro * 8;
                    }
                }
#pragma unroll
            for (int off = 4; off <= 16; off <<= 1) {
                float om = __shfl_xor_sync(0xffffffffu, lm, off);
                int oa = __shfl_xor_sync(0xffffffffu, la, off);
                if (om > lm || (om == lm && oa < la)) { lm = om; la = oa; }
            }
            if (gid == 0) {
                int tcol = wn + (nt << 3) + (t4 << 1) + c;
                wmax[(wm >> 6) * 128 + tcol] = lm;
                warg[(wm >> 6) * 128 + tcol] = la;
            }
        }
    }
    __syncthreads();
    float fm = 0.0f;
    int fa = 0;
    if (tid < 128) {
        float ma = wmax[tid], mb = wmax[128 + tid];
        if (mb > ma) { fm = mb; fa = warg[128 + tid]; }
        else { fm = ma; fa = warg[tid]; }
        bmx[tid] = fm;
    }
    __syncthreads();

    // per-token sumexp
#pragma unroll
    for (int nt = 0; nt < 4; nt++) {
#pragma unroll
        for (int c = 0; c < 2; c++) {
            int tcol = wn + (nt << 3) + (t4 << 1) + c;
            float mx = bmx[tcol];
            float s = 0.0f;
#pragma unroll
            for (int mt = 0; mt < 4; mt++)
#pragma unroll
                for (int ro = 0; ro < 2; ro++)
                    s += __expf(acc[mt][nt][ro * 2 + c] - mx);
#pragma unroll
            for (int off = 4; off <= 16; off <<= 1)
                s += __shfl_xor_sync(0xffffffffu, s, off);
            if (gid == 0) wsum[(wm >> 6) * 128 + tcol] = s;
        }
    }
    __syncthreads();
    if (tid < 128) {
        size_t tok = (size_t)(n0 + tid);
        g_pmax[tok * NVT + vt] = fm;
        g_parg[tok * NVT + vt] = fa;
        g_psum[tok * NVT + vt] = wsum[tid] + wsum[128 + tid];
    }
}

// ------------------ persistent BiLSTM layer scan (v1, proven) ------------------
__global__ __launch_bounds__(128) void k_scan(const float* __restrict__ gx,
                                              const float* __restrict__ whh,
                                              const float* __restrict__ mask,
                                              float* __restrict__ out) {
    __shared__ float Hs[32 * 129];
    __shared__ float Ws[128 * 17];

    int tid = threadIdx.x;
    int bid = blockIdx.x;
    int d = bid >> 6;
    int ks = (bid >> 4) & 3;
    int gt = bid & 15;
    int g0 = gt << 7;
    int k0 = ks << 7;
    const float* whhd = whh + (size_t)d * NG * NH;

    int tg = tid >> 3;
    int tb = tid & 7;

    int jt = bid & 63;
    int jl = tid & 7;
    int bq = tid >> 3;

    for (int s = 0; s < NL; s++) {
        {
            int hb = tid >> 2;
            int hk = (tid & 3) << 5;
            const float* hp = g_h + (size_t)(d * NB + hb) * NH + k0 + hk;
            float* dst = &Hs[hb * 129 + hk];
#pragma unroll
            for (int q = 0; q < 8; q++) {
                float4 v = __ldcg((const float4*)(hp + q * 4));
                dst[q * 4 + 0] = v.x; dst[q * 4 + 1] = v.y;
                dst[q * 4 + 2] = v.z; dst[q * 4 + 3] = v.w;
            }
        }
        float acc[8][4];
#pragma unroll
        for (int i = 0; i < 8; i++)
#pragma unroll
            for (int j = 0; j < 4; j++) acc[i][j] = 0.0f;

        const float* wrow = whhd + (size_t)(g0 + tid) * NH + k0;
        for (int kc = 0; kc < 8; kc++) {
            __syncthreads();
            {
                float4 w0 = *(const float4*)(wrow + kc * 16 + 0);
                float4 w1 = *(const float4*)(wrow + kc * 16 + 4);
                float4 w2 = *(const float4*)(wrow + kc * 16 + 8);
                float4 w3 = *(const float4*)(wrow + kc * 16 + 12);
                float* wd = &Ws[tid * 17];
                wd[0] = w0.x;  wd[1] = w0.y;  wd[2] = w0.z;  wd[3] = w0.w;
                wd[4] = w1.x;  wd[5] = w1.y;  wd[6] = w1.z;  wd[7] = w1.w;
                wd[8] = w2.x;  wd[9] = w2.y;  wd[10] = w2.z; wd[11] = w2.w;
                wd[12] = w3.x; wd[13] = w3.y; wd[14] = w3.z; wd[15] = w3.w;
            }
            __syncthreads();
#pragma unroll
            for (int k = 0; k < 16; k++) {
                float hv[4];
#pragma unroll
                for (int j = 0; j < 4; j++)
                    hv[j] = Hs[(tb * 4 + j) * 129 + (kc << 4) + k];
#pragma unroll
                for (int i = 0; i < 8; i++) {
                    float w = Ws[((tg << 3) + i) * 17 + k];
#pragma unroll
                    for (int j = 0; j < 4; j++) acc[i][j] += w * hv[j];
                }
            }
        }
        {
            size_t pbase = ((size_t)(d * 4 + ks) * NG + g0) * NB;
#pragma unroll
            for (int i = 0; i < 8; i++)
#pragma unroll
                for (int j = 0; j < 4; j++)
                    g_part[pbase + (size_t)((tg << 3) + i) * NB + tb * 4 + j] = acc[i][j];
        }
        __threadfence();
        gridbar();

        int t = d ? (NL - 1 - s) : s;
#pragma unroll
        for (int rep = 0; rep < 2; rep++) {
            int b = bq + (rep << 4);
            int j = (jt << 3) + jl;
            float gate[4];
#pragma unroll
            for (int gi = 0; gi < 4; gi++) {
                int g = gi * NH + j;
                float v = gx[((size_t)d * NTOK + (size_t)b * NL + t) * NG + g];
#pragma unroll
                for (int kss = 0; kss < 4; kss++)
                    v += __ldcg(&g_part[((size_t)(d * 4 + kss) * NG + g) * NB + b]);
                gate[gi] = v;
            }
            float ivg = sigf(gate[0]);
            float fvg = sigf(gate[1]);
            float gvg = tanhf_fast(gate[2]);
            float ovg = sigf(gate[3]);
            size_t hidx = (size_t)(d * NB + b) * NH + j;
            float cold = __ldcg(&g_c[hidx]);
            float cnew = fvg * cold + ivg * gvg;
            float hnew = ovg * tanhf_fast(cnew);
            float mt = mask[b * NL + t];
            float hold = __ldcg(&g_h[hidx]);
            float hh = hold + (hnew - hold) * mt;
            float cc = cold + (cnew - cold) * mt;
            g_c[hidx] = cc;
            g_h[hidx] = hh;
            out[((size_t)b * NL + t) * 1024 + d * NH + j] = hh;
        }
        __threadfence();
        gridbar();
    }
}

// ------------------ per-token combine ------------------
__global__ __launch_bounds__(256) void k_comb(const float* __restrict__ w2,
                                              const float* __restrict__ b2,
                                              const int* __restrict__ tgt,
                                              const float* __restrict__ cew,
                                              float* __restrict__ dout) {
    int warp = threadIdx.x >> 5, lane = threadIdx.x & 31;
    int m = blockIdx.x * 8 + warp;

    float lm = -1e30f, ls = 0.0f;
    int la = 0;
    for (int vt = lane; vt < NVT; vt += 32) {
        float tmx = g_pmax[(size_t)m * NVT + vt];
        float tsm = g_psum[(size_t)m * NVT + vt];
        int tag = g_parg[(size_t)m * NVT + vt];
        if (tmx > lm) {
            ls = ls * __expf(lm - tmx) + tsm;
            lm = tmx;
            la = tag;
        } else {
            ls += tsm * __expf(tmx - lm);
        }
    }
#pragma unroll
    for (int off = 16; off; off >>= 1) {
        float om = __shfl_down_sync(0xffffffffu, lm, off);
        float os = __shfl_down_sync(0xffffffffu, ls, off);
        int oa = __shfl_down_sync(0xffffffffu, la, off);
        float nm = fmaxf(lm, om);
        float ns = ls * __expf(lm - nm) + os * __expf(om - nm);
        int na = (om > lm) ? oa : ((om == lm && oa < la) ? oa : la);
        lm = nm; ls = ns; la = na;
    }

    int tg = tgt[m];
    float4 hv = *(const float4*)&g_hid[(size_t)m * 128 + lane * 4];
    float4 wv = *(const float4*)&w2[(size_t)tg * 128 + lane * 4];
    float dp = hv.x * wv.x + hv.y * wv.y + hv.z * wv.z + hv.w * wv.w;
#pragma unroll
    for (int off = 16; off; off >>= 1) dp += __shfl_down_sync(0xffffffffu, dp, off);

    if (lane == 0) {
        float logit_t = dp + b2[tg];
        float lse = lm + logf(ls);
        float nll = lse - logit_t;
        float w = cew[tg];
        g_nllw[m] = nll * w;
        g_wtok[m] = w;
        dout[1 + m] = (float)la;
    }
}

// ------------------ final loss reduce ------------------
__global__ __launch_bounds__(256) void k_loss(float* __restrict__ dout) {
    __shared__ float s1[256];
    __shared__ float s2[256];
    int tid = threadIdx.x;
    float a = 0.0f, b = 0.0f;
    for (int i = tid; i < NTOK; i += 256) { a += g_nllw[i]; b += g_wtok[i]; }
    s1[tid] = a; s2[tid] = b;
    __syncthreads();
    for (int off = 128; off; off >>= 1) {
        if (tid < off) { s1[tid] += s1[tid + off]; s2[tid] += s2[tid + off]; }
        __syncthreads();
    }
    if (tid == 0) dout[0] = s1[0] / s2[0];
}

// ------------------ launch ------------------
extern "C" void kernel_launch(void* const* d_in, const int* in_sizes, int n_in,
                              void* d_out, int out_size) {
    const int* inp_word = (const int*)d_in[0];
    const float* inp_mask = (const float*)d_in[1];
    const int* tgt_word = (const int*)d_in[3];
    const float* emb = (const float*)d_in[4];
    const float* w_ih0 = (const float*)d_in[5];
    const float* w_hh0 = (const float*)d_in[6];
    const float* b0 = (const float*)d_in[7];
    const float* w_ih = (const float*)d_in[8];
    const float* w_hh = (const float*)d_in[9];
    const float* bb = (const float*)d_in[10];
    const float* dec_w1 = (const float*)d_in[11];
    const float* dec_b1 = (const float*)d_in[12];
    const float* dec_w2 = (const float*)d_in[13];
    const float* dec_b2 = (const float*)d_in[14];
    const float* cew = (const float*)d_in[15];
    float* out = (float*)d_out;

    float *pgx, *pA, *pB, *phid, *pwh, *pwl, *pah, *pal;
    cudaGetSymbolAddress((void**)&pgx, g_gx);
    cudaGetSymbolAddress((void**)&pA, g_bufA);
    cudaGetSymbolAddress((void**)&pB, g_bufB);
    cudaGetSymbolAddress((void**)&phid, g_hid);
    cudaGetSymbolAddress((void**)&pwh, g_wh);
    cudaGetSymbolAddress((void**)&pwl, g_wl);
    cudaGetSymbolAddress((void**)&pah, g_ah);
    cudaGetSymbolAddress((void**)&pal, g_al);

    const int gsm = 2 * STAGE * 4;   // 81920 bytes
    cudaFuncSetAttribute(k_gemm2, cudaFuncAttributeMaxDynamicSharedMemorySize, gsm);
    cudaFuncSetAttribute(k_dec2m, cudaFuncAttributeMaxDynamicSharedMemorySize, gsm);

    // 0. split all weights into tf32 hi/lo planes
    k_split<<<512, 256>>>(w_ih0, pwh + OFF_WIH0, pwl + OFF_WIH0, 524288 / 4);
    k_split<<<8192, 256>>>(w_ih, pwh + OFF_WIH1, pwl + OFF_WIH1, 8388608 / 4);
    k_split<<<128, 256>>>(dec_w1, pwh + OFF_W1, pwl + OFF_W1, 131072 / 4);
    k_split<<<4000, 256>>>(dec_w2, pwh + OFF_W2, pwl + OFF_W2, 4096000 / 4);

    // 1. embedding (split planes, K=128)
    k_embed<<<(NTOK * NE) / 256, 256>>>(inp_word, emb);

    // 2. layer 0
    k_gemm2<<<dim3(NG / 128, NTOK / 128, 2), 256, gsm>>>(
        pah, pal, pwh + OFF_WIH0, pwl + OFF_WIH0, b0, pgx,
        NE, NG, (long long)NG * NE, NG, (long long)NTOK * NG, 0);
    k_zero<<<128, 256>>>();
    k_scan<<<128, 128>>>(pgx, w_hh0, inp_mask, pA);

    // 3. layer 1
    k_split<<<4096, 256>>>(pA, pah, pal, (NTOK * 1024) / 4);
    k_gemm2<<<dim3(NG / 128, NTOK / 128, 2), 256, gsm>>>(
        pah, pal, pwh + OFF_WIH1, pwl + OFF_WIH1, bb, pgx,
        1024, NG, (long long)NG * 1024, NG, (long long)NTOK * NG, 0);
    k_zero<<<128, 256>>>();
    k_scan<<<128, 128>>>(pgx, w_hh, inp_mask, pB);

    // 4. layer 2
    k_split<<<4096, 256>>>(pB, pah, pal, (NTOK * 1024) / 4);
    k_gemm2<<<dim3(NG / 128, NTOK / 128, 2), 256, gsm>>>(
        pah, pal, pwh + OFF_WIH1 + 4194304, pwl + OFF_WIH1 + 4194304,
        bb + 2 * NG, pgx,
        1024, NG, (long long)NG * 1024, NG, (long long)NTOK * NG, 0);
    k_zero<<<128, 256>>>();
    k_scan<<<128, 128>>>(pgx, w_hh + (size_t)2 * NG * NH, inp_mask, pA);

    // 5. decoder layer 1 (relu, writes g_hid + split planes)
    k_split<<<4096, 256>>>(pA, pah, pal, (NTOK * 1024) / 4);
    k_gemm2<<<dim3(1, NTOK / 128, 1), 256, gsm>>>(
        pah, pal, pwh + OFF_W1, pwl + OFF_W1, dec_b1, phid,
        1024, 128, 0, 0, 0, 2);

    // 6. decoder layer 2 (mma) + fused online softmax partials
    k_dec2m<<<dim3(NVT, NTOK / 128), 256, gsm>>>(dec_b2);

    // 7. per-token combine
    k_comb<<<NTOK / 8, 256>>>(dec_w2, dec_b2, tgt_word, cew, out);

    // 8. loss reduce
    k_loss<<<1, 256>>>(out);
}

// round 8
// speedup vs baseline: 1.5828x; 1.3889x over previous
#include <cuda_runtime.h>
#include <math.h>
#include <stdint.h>

#define NB 32
#define NL 128
#define NH 512
#define NG 2048
#define NV 32000
#define NE 128
#define NTOK 4096
#define NVT 250

// weight-plane arena offsets (floats)
#define OFF_WIH0 0
#define OFF_WIH1 524288
#define OFF_W1   8912896
#define OFF_W2   9043968
#define WARENA   13139968

// ------------------ scratch ------------------
__device__ float g_wh[WARENA];
__device__ float g_wl[WARENA];
__device__ float g_whhh[3 * 2 * NG * NH];
__device__ float g_whhl[3 * 2 * NG * NH];
__device__ float g_ah[NTOK * 1024];
__device__ float g_al[NTOK * 1024];
__device__ float g_gx[2u * NTOK * NG];          // [dir][m][g], m = b*128+t
__device__ float g_bufA[NTOK * 1024];
__device__ float g_bufB[NTOK * 1024];
__device__ float g_hid[NTOK * 128];
__device__ float g_hidh[NTOK * 128];
__device__ float g_hidl[NTOK * 128];
__device__ float g_hph[2 * NB * NH];
__device__ float g_hpl[2 * NB * NH];
__device__ float g_part[2 * 4 * NG * NB];       // [dir][ks][g][b]
__device__ float g_pmax[(size_t)NTOK * NVT];
__device__ float g_psum[(size_t)NTOK * NVT];
__device__ int   g_parg[(size_t)NTOK * NVT];
__device__ float g_nllw[NTOK];
__device__ float g_wtok[NTOK];
__device__ unsigned int g_barcnt;

// ------------------ helpers ------------------
__device__ __forceinline__ float sigf(float x) {
    return 1.0f / (1.0f + __expf(-x));
}
__device__ __forceinline__ float tanhf_fast(float x) {
    float e = __expf(-2.0f * fabsf(x));
    float r = (1.0f - e) / (1.0f + e);
    return copysignf(r, x);
}

__device__ __forceinline__ void gridbar() {
    __syncthreads();
    if (threadIdx.x == 0) {
        unsigned int t = atomicAdd(&g_barcnt, 1u);
        unsigned int need = ((t >> 7) + 1u) << 7;
        while (*((volatile unsigned int*)&g_barcnt) < need) {
            __nanosleep(32);
        }
    }
    __syncthreads();
}

__device__ __forceinline__ void tf32split(float x, float& hi, float& lo) {
    unsigned hb;
    asm("cvt.rna.tf32.f32 %0, %1;" : "=r"(hb) : "f"(x));
    float hf = __uint_as_float(hb);
    float l = x - hf;
    unsigned lb;
    asm("cvt.rna.tf32.f32 %0, %1;" : "=r"(lb) : "f"(l));
    hi = hf;
    lo = __uint_as_float(lb);
}

#define MMA_TF32(c, a, b)                                                     \
    asm volatile(                                                             \
        "mma.sync.aligned.m16n8k8.row.col.f32.tf32.tf32.f32 "                 \
        "{%0,%1,%2,%3}, {%4,%5,%6,%7}, {%8,%9}, {%0,%1,%2,%3};"               \
        : "+f"((c)[0]), "+f"((c)[1]), "+f"((c)[2]), "+f"((c)[3])              \
        : "r"((a)[0]), "r"((a)[1]), "r"((a)[2]), "r"((a)[3]),                 \
          "r"((b)[0]), "r"((b)[1]))

__device__ __forceinline__ void cp16(uint32_t dst, const float* src) {
    asm volatile("cp.async.cg.shared.global [%0], [%1], 16;" :: "r"(dst), "l"(src));
}
#define CP_COMMIT() asm volatile("cp.async.commit_group;")
#define CP_WAIT1()  asm volatile("cp.async.wait_group 1;")
#define CP_WAIT0()  asm volatile("cp.async.wait_group 0;")

// gemm stage layout: 4 planes (AH, AL, BH, BL) x 128 rows x 20 floats
#define PLANE 2560
#define STAGE 10240

// ------------------ split kernel ------------------
__global__ __launch_bounds__(256) void k_split(const float* __restrict__ s,
                                               float* __restrict__ dh,
                                               float* __restrict__ dl, int n4) {
    int i = blockIdx.x * 256 + threadIdx.x;
    if (i < n4) {
        float4 v = ((const float4*)s)[i];
        float4 h4, l4;
        tf32split(v.x, h4.x, l4.x);
        tf32split(v.y, h4.y, l4.y);
        tf32split(v.z, h4.z, l4.z);
        tf32split(v.w, h4.w, l4.w);
        ((float4*)dh)[i] = h4;
        ((float4*)dl)[i] = l4;
    }
}

// ------------------ embedding (writes split planes) ------------------
__global__ __launch_bounds__(256) void k_embed(const int* __restrict__ w,
                                               const float* __restrict__ emb) {
    int i = blockIdx.x * 256 + threadIdx.x;
    float v = emb[(size_t)w[i >> 7] * NE + (i & 127)];
    float h, l;
    tf32split(v, h, l);
    g_ah[i] = h;
    g_al[i] = l;
}

// ------------------ zero h planes + barrier ------------------
__global__ __launch_bounds__(256) void k_zero() {
    int i = blockIdx.x * 256 + threadIdx.x;
    if (i < 2 * NB * NH) { g_hph[i] = 0.0f; g_hpl[i] = 0.0f; }
    if (i == 0) g_barcnt = 0u;
}

// ------------------ 3xTF32 mma GEMM, presplit inputs, cp.async pipeline ----
__global__ __launch_bounds__(256) void k_gemm2(const float* __restrict__ Ahp,
                                               const float* __restrict__ Alp,
                                               const float* __restrict__ Whp,
                                               const float* __restrict__ Wlp,
                                               const float* __restrict__ bias,
                                               float* __restrict__ C,
                                               int K, int N,
                                               long long wStr, long long bStr,
                                               long long cStr, int mode) {
    extern __shared__ float smf[];
    uint32_t smb = (uint32_t)__cvta_generic_to_shared(smf);

    int d = blockIdx.z;
    Whp += (size_t)d * wStr;
    Wlp += (size_t)d * wStr;
    bias += (size_t)d * bStr;
    C += (size_t)d * cStr;

    int tid = threadIdx.x;
    int m0 = blockIdx.y << 7, n0 = blockIdx.x << 7;
    int lr = tid >> 2, lkq = (tid & 3) << 2;

    const float* pA0h = Ahp + (size_t)(m0 + lr) * K + lkq;
    const float* pA1h = Ahp + (size_t)(m0 + lr + 64) * K + lkq;
    const float* pA0l = Alp + (size_t)(m0 + lr) * K + lkq;
    const float* pA1l = Alp + (size_t)(m0 + lr + 64) * K + lkq;
    const float* pB0h = Whp + (size_t)(n0 + lr) * K + lkq;
    const float* pB1h = Whp + (size_t)(n0 + lr + 64) * K + lkq;
    const float* pB0l = Wlp + (size_t)(n0 + lr) * K + lkq;
    const float* pB1l = Wlp + (size_t)(n0 + lr + 64) * K + lkq;

    uint32_t o0 = (uint32_t)((0 * PLANE + lr * 20 + lkq) * 4);
    uint32_t o1 = (uint32_t)((0 * PLANE + (lr + 64) * 20 + lkq) * 4);
    uint32_t o2 = (uint32_t)((1 * PLANE + lr * 20 + lkq) * 4);
    uint32_t o3 = (uint32_t)((1 * PLANE + (lr + 64) * 20 + lkq) * 4);
    uint32_t o4 = (uint32_t)((2 * PLANE + lr * 20 + lkq) * 4);
    uint32_t o5 = (uint32_t)((2 * PLANE + (lr + 64) * 20 + lkq) * 4);
    uint32_t o6 = (uint32_t)((3 * PLANE + lr * 20 + lkq) * 4);
    uint32_t o7 = (uint32_t)((3 * PLANE + (lr + 64) * 20 + lkq) * 4);

    int wid = tid >> 5, lane = tid & 31;
    int gid = lane >> 2, t4 = lane & 3;
    int wm = (wid >> 2) << 6;
    int wn = (wid & 3) << 5;

    float acc[4][4][4];
#pragma unroll
    for (int mt = 0; mt < 4; mt++)
#pragma unroll
        for (int nt = 0; nt < 4; nt++)
#pragma unroll
            for (int r = 0; r < 4; r++) acc[mt][nt][r] = 0.0f;

    int T = K >> 4;
    {
        uint32_t b = smb;
        cp16(b + o0, pA0h); cp16(b + o1, pA1h);
        cp16(b + o2, pA0l); cp16(b + o3, pA1l);
        cp16(b + o4, pB0h); cp16(b + o5, pB1h);
        cp16(b + o6, pB0l); cp16(b + o7, pB1l);
        CP_COMMIT();
    }

    for (int kt = 0; kt < T; kt++) {
        int s = kt & 1;
        if (kt + 1 < T) {
            int ko = (kt + 1) << 4;
            uint32_t b = smb + (uint32_t)((s ^ 1) * STAGE * 4);
            cp16(b + o0, pA0h + ko); cp16(b + o1, pA1h + ko);
            cp16(b + o2, pA0l + ko); cp16(b + o3, pA1l + ko);
            cp16(b + o4, pB0h + ko); cp16(b + o5, pB1h + ko);
            cp16(b + o6, pB0l + ko); cp16(b + o7, pB1l + ko);
            CP_COMMIT();
            CP_WAIT1();
        } else {
            CP_WAIT0();
        }
        __syncthreads();
        const float* S = smf + s * STAGE;

#pragma unroll
        for (int k8 = 0; k8 < 16; k8 += 8) {
            unsigned ah[4][4], al[4][4];
#pragma unroll
            for (int mt = 0; mt < 4; mt++) {
                int r0i = (wm + (mt << 4) + gid) * 20 + k8 + t4;
                int r1i = (wm + (mt << 4) + gid + 8) * 20 + k8 + t4;
                ah[mt][0] = __float_as_uint(S[r0i]);
                ah[mt][1] = __float_as_uint(S[r1i]);
                ah[mt][2] = __float_as_uint(S[r0i + 4]);
                ah[mt][3] = __float_as_uint(S[r1i + 4]);
                al[mt][0] = __float_as_uint(S[PLANE + r0i]);
                al[mt][1] = __float_as_uint(S[PLANE + r1i]);
                al[mt][2] = __float_as_uint(S[PLANE + r0i + 4]);
                al[mt][3] = __float_as_uint(S[PLANE + r1i + 4]);
            }
            unsigned bh[4][2], bl[4][2];
#pragma unroll
            for (int nt = 0; nt < 4; nt++) {
                int ci = (wn + (nt << 3) + gid) * 20 + k8 + t4;
                bh[nt][0] = __float_as_uint(S[2 * PLANE + ci]);
                bh[nt][1] = __float_as_uint(S[2 * PLANE + ci + 4]);
                bl[nt][0] = __float_as_uint(S[3 * PLANE + ci]);
                bl[nt][1] = __float_as_uint(S[3 * PLANE + ci + 4]);
            }
#pragma unroll
            for (int mt = 0; mt < 4; mt++)
#pragma unroll
                for (int nt = 0; nt < 4; nt++) {
                    MMA_TF32(acc[mt][nt], ah[mt], bh[nt]);
                    MMA_TF32(acc[mt][nt], ah[mt], bl[nt]);
                    MMA_TF32(acc[mt][nt], al[mt], bh[nt]);
                }
        }
        __syncthreads();
    }

#pragma unroll
    for (int mt = 0; mt < 4; mt++) {
#pragma unroll
        for (int nt = 0; nt < 4; nt++) {
            int m = m0 + wm + (mt << 4) + gid;
            int n = n0 + wn + (nt << 3) + (t4 << 1);
            float bv0 = bias[n], bv1 = bias[n + 1];
            float v0 = acc[mt][nt][0] + bv0;
            float v1 = acc[mt][nt][1] + bv1;
            float v2 = acc[mt][nt][2] + bv0;
            float v3 = acc[mt][nt][3] + bv1;
            if (mode) {
                v0 = fmaxf(v0, 0.0f); v1 = fmaxf(v1, 0.0f);
                v2 = fmaxf(v2, 0.0f); v3 = fmaxf(v3, 0.0f);
            }
            float2 p0 = {v0, v1};
            float2 p1 = {v2, v3};
            *(float2*)(C + (size_t)m * N + n) = p0;
            *(float2*)(C + (size_t)(m + 8) * N + n) = p1;
            if (mode == 2) {
                float h, l;
                size_t i0 = (size_t)m * N + n;
                size_t i1 = (size_t)(m + 8) * N + n;
                tf32split(v0, h, l); g_hidh[i0] = h;     g_hidl[i0] = l;
                tf32split(v1, h, l); g_hidh[i0 + 1] = h; g_hidl[i0 + 1] = l;
                tf32split(v2, h, l); g_hidh[i1] = h;     g_hidl[i1] = l;
                tf32split(v3, h, l); g_hidh[i1 + 1] = h; g_hidl[i1 + 1] = l;
            }
        }
    }
}

// ------------------ decoder2 mma: logits tile + online softmax partials ----
__global__ __launch_bounds__(256) void k_dec2m(const float* __restrict__ b2) {
    extern __shared__ float smf[];
    uint32_t smb = (uint32_t)__cvta_generic_to_shared(smf);
    __shared__ float wmax[256];
    __shared__ int   warg[256];
    __shared__ float wsum[256];
    __shared__ float bmx[128];

    const float* Ahp = g_wh + OFF_W2;
    const float* Alp = g_wl + OFF_W2;

    int tid = threadIdx.x;
    int vt = blockIdx.x;
    int v0 = vt << 7;
    int n0 = blockIdx.y << 7;
    int lr = tid >> 2, lkq = (tid & 3) << 2;
    const int K = 128;

    const float* pA0h = Ahp + (size_t)(v0 + lr) * K + lkq;
    const float* pA1h = Ahp + (size_t)(v0 + lr + 64) * K + lkq;
    const float* pA0l = Alp + (size_t)(v0 + lr) * K + lkq;
    const float* pA1l = Alp + (size_t)(v0 + lr + 64) * K + lkq;
    const float* pB0h = g_hidh + (size_t)(n0 + lr) * K + lkq;
    const float* pB1h = g_hidh + (size_t)(n0 + lr + 64) * K + lkq;
    const float* pB0l = g_hidl + (size_t)(n0 + lr) * K + lkq;
    const float* pB1l = g_hidl + (size_t)(n0 + lr + 64) * K + lkq;

    uint32_t o0 = (uint32_t)((0 * PLANE + lr * 20 + lkq) * 4);
    uint32_t o1 = (uint32_t)((0 * PLANE + (lr + 64) * 20 + lkq) * 4);
    uint32_t o2 = (uint32_t)((1 * PLANE + lr * 20 + lkq) * 4);
    uint32_t o3 = (uint32_t)((1 * PLANE + (lr + 64) * 20 + lkq) * 4);
    uint32_t o4 = (uint32_t)((2 * PLANE + lr * 20 + lkq) * 4);
    uint32_t o5 = (uint32_t)((2 * PLANE + (lr + 64) * 20 + lkq) * 4);
    uint32_t o6 = (uint32_t)((3 * PLANE + lr * 20 + lkq) * 4);
    uint32_t o7 = (uint32_t)((3 * PLANE + (lr + 64) * 20 + lkq) * 4);

    int wid = tid >> 5, lane = tid & 31;
    int gid = lane >> 2, t4 = lane & 3;
    int wm = (wid >> 2) << 6;
    int wn = (wid & 3) << 5;

    float acc[4][4][4];
#pragma unroll
    for (int mt = 0; mt < 4; mt++)
#pragma unroll
        for (int nt = 0; nt < 4; nt++)
#pragma unroll
            for (int r = 0; r < 4; r++) acc[mt][nt][r] = 0.0f;

    const int T = 8;
    {
        uint32_t b = smb;
        cp16(b + o0, pA0h); cp16(b + o1, pA1h);
        cp16(b + o2, pA0l); cp16(b + o3, pA1l);
        cp16(b + o4, pB0h); cp16(b + o5, pB1h);
        cp16(b + o6, pB0l); cp16(b + o7, pB1l);
        CP_COMMIT();
    }
    for (int kt = 0; kt < T; kt++) {
        int s = kt & 1;
        if (kt + 1 < T) {
            int ko = (kt + 1) << 4;
            uint32_t b = smb + (uint32_t)((s ^ 1) * STAGE * 4);
            cp16(b + o0, pA0h + ko); cp16(b + o1, pA1h + ko);
            cp16(b + o2, pA0l + ko); cp16(b + o3, pA1l + ko);
            cp16(b + o4, pB0h + ko); cp16(b + o5, pB1h + ko);
            cp16(b + o6, pB0l + ko); cp16(b + o7, pB1l + ko);
            CP_COMMIT();
            CP_WAIT1();
        } else {
            CP_WAIT0();
        }
        __syncthreads();
        const float* S = smf + s * STAGE;
#pragma unroll
        for (int k8 = 0; k8 < 16; k8 += 8) {
            unsigned ah[4][4], al[4][4];
#pragma unroll
            for (int mt = 0; mt < 4; mt++) {
                int r0i = (wm + (mt << 4) + gid) * 20 + k8 + t4;
                int r1i = (wm + (mt << 4) + gid + 8) * 20 + k8 + t4;
                ah[mt][0] = __float_as_uint(S[r0i]);
                ah[mt][1] = __float_as_uint(S[r1i]);
                ah[mt][2] = __float_as_uint(S[r0i + 4]);
                ah[mt][3] = __float_as_uint(S[r1i + 4]);
                al[mt][0] = __float_as_uint(S[PLANE + r0i]);
                al[mt][1] = __float_as_uint(S[PLANE + r1i]);
                al[mt][2] = __float_as_uint(S[PLANE + r0i + 4]);
                al[mt][3] = __float_as_uint(S[PLANE + r1i + 4]);
            }
            unsigned bh[4][2], bl[4][2];
#pragma unroll
            for (int nt = 0; nt < 4; nt++) {
                int ci = (wn + (nt << 3) + gid) * 20 + k8 + t4;
                bh[nt][0] = __float_as_uint(S[2 * PLANE + ci]);
                bh[nt][1] = __float_as_uint(S[2 * PLANE + ci + 4]);
                bl[nt][0] = __float_as_uint(S[3 * PLANE + ci]);
                bl[nt][1] = __float_as_uint(S[3 * PLANE + ci + 4]);
            }
#pragma unroll
            for (int mt = 0; mt < 4; mt++)
#pragma unroll
                for (int nt = 0; nt < 4; nt++) {
                    MMA_TF32(acc[mt][nt], ah[mt], bh[nt]);
                    MMA_TF32(acc[mt][nt], ah[mt], bl[nt]);
                    MMA_TF32(acc[mt][nt], al[mt], bh[nt]);
                }
        }
        __syncthreads();
    }

    float bvv[4][2];
#pragma unroll
    for (int mt = 0; mt < 4; mt++) {
        bvv[mt][0] = b2[v0 + wm + (mt << 4) + gid];
        bvv[mt][1] = b2[v0 + wm + (mt << 4) + gid + 8];
    }
#pragma unroll
    for (int mt = 0; mt < 4; mt++)
#pragma unroll
        for (int nt = 0; nt < 4; nt++) {
            acc[mt][nt][0] += bvv[mt][0];
            acc[mt][nt][1] += bvv[mt][0];
            acc[mt][nt][2] += bvv[mt][1];
            acc[mt][nt][3] += bvv[mt][1];
        }

#pragma unroll
    for (int nt = 0; nt < 4; nt++) {
#pragma unroll
        for (int c = 0; c < 2; c++) {
            float lm = -1e30f;
            int la = 0;
#pragma unroll
            for (int mt = 0; mt < 4; mt++)
#pragma unroll
                for (int ro = 0; ro < 2; ro++) {
                    float lg = acc[mt][nt][ro * 2 + c];
                    if (lg > lm) {
                        lm = lg;
                        la = v0 + wm + (mt << 4) + gid + ro * 8;
                    }
                }
#pragma unroll
            for (int off = 4; off <= 16; off <<= 1) {
                float om = __shfl_xor_sync(0xffffffffu, lm, off);
                int oa = __shfl_xor_sync(0xffffffffu, la, off);
                if (om > lm || (om == lm && oa < la)) { lm = om; la = oa; }
            }
            if (gid == 0) {
                int tcol = wn + (nt << 3) + (t4 << 1) + c;
                wmax[(wm >> 6) * 128 + tcol] = lm;
                warg[(wm >> 6) * 128 + tcol] = la;
            }
        }
    }
    __syncthreads();
    float fm = 0.0f;
    int fa = 0;
    if (tid < 128) {
        float ma = wmax[tid], mb = wmax[128 + tid];
        if (mb > ma) { fm = mb; fa = warg[128 + tid]; }
        else { fm = ma; fa = warg[tid]; }
        bmx[tid] = fm;
    }
    __syncthreads();

#pragma unroll
    for (int nt = 0; nt < 4; nt++) {
#pragma unroll
        for (int c = 0; c < 2; c++) {
            int tcol = wn + (nt << 3) + (t4 << 1) + c;
            float mx = bmx[tcol];
            float s = 0.0f;
#pragma unroll
            for (int mt = 0; mt < 4; mt++)
#pragma unroll
                for (int ro = 0; ro < 2; ro++)
                    s += __expf(acc[mt][nt][ro * 2 + c] - mx);
#pragma unroll
            for (int off = 4; off <= 16; off <<= 1)
                s += __shfl_xor_sync(0xffffffffu, s, off);
            if (gid == 0) wsum[(wm >> 6) * 128 + tcol] = s;
        }
    }
    __syncthreads();
    if (tid < 128) {
        size_t tok = (size_t)(n0 + tid);
        g_pmax[tok * NVT + vt] = fm;
        g_parg[tok * NVT + vt] = fa;
        g_psum[tok * NVT + vt] = wsum[tid] + wsum[128 + tid];
    }
}

// ------------------ persistent BiLSTM scan v4: tensor-core partial GEMM ----
// 128 blocks x 256 threads. Block=(d, ks in 4, gt in 16): partial gates
// [128 rows] x [32 b] over k-slice 128, mma m16n8k8 3xTF32, Whh tile
// persistent in smem. Combine: block=(d, jt in 64), thread owns (b, j),
// c/h in registers, writes split h planes. 2 grid barriers per step (v1 topology).
__global__ __launch_bounds__(256) void k_scan4(const float* __restrict__ gx,
                                               const float* __restrict__ mask,
                                               float* __restrict__ out,
                                               const float* __restrict__ whh_h,
                                               const float* __restrict__ whh_l) {
    extern __shared__ float sm[];
    float* Wh = sm;                         // [128][132]
    float* Wl = sm + 16896;                 // [128][132]
    float* Hh = sm + 33792;                 // [32][132]
    float* Hl = sm + 33792 + 4224;          // [32][132]
    uint32_t smb = (uint32_t)__cvta_generic_to_shared(sm);

    int tid = threadIdx.x;
    int bid = blockIdx.x;
    int d = bid >> 6;
    int ks = (bid >> 4) & 3;
    int gt = bid & 15;
    int g0 = gt << 7;
    int k0 = ks << 7;

    // preload Whh hi/lo tile (once per layer)
#pragma unroll
    for (int p = 0; p < 2; p++) {
        const float* src = p ? whh_l : whh_h;
        float* dst = p ? Wl : Wh;
#pragma unroll
        for (int j = 0; j < 16; j++) {
            int idx = tid + j * 256;             // f4 index, 4096/plane
            int row = idx >> 5;
            int c = (idx & 31) << 2;
            float4 v = __ldg((const float4*)(src + (size_t)(d * NG + g0 + row) * NH + k0 + c));
            *(float4*)&dst[row * 132 + c] = v;
        }
    }

    int wid = tid >> 5, lane = tid & 31;
    int gid = lane >> 2, t4 = lane & 3;
    int rowbase = wid << 4;                      // warp m-tile: 16 rows

    // combine role
    int jt = bid & 63;
    int cb = tid & 31;
    int jl = tid >> 5;
    int cj = (jt << 3) + jl;
    float creg = 0.0f, hreg = 0.0f;

    __syncthreads();

    for (int s = 0; s < NL; s++) {
        int t = d ? (NL - 1 - s) : s;

        // ---- stage h planes (32x128 x 2) via cp.async ----
        {
            int idx = tid;
#pragma unroll
            for (int j = 0; j < 8; j++, idx += 256) {
                int p = idx >> 10;
                int rem = idx & 1023;
                int row = rem >> 5;
                int c = (rem & 31) << 2;
                const float* src = (p ? g_hpl : g_hph) + (size_t)(d * NB + row) * NH + k0 + c;
                uint32_t dst = smb + (uint32_t)(((p ? 38016 : 33792) + row * 132 + c) * 4);
                cp16(dst, src);
            }
            CP_COMMIT();
            CP_WAIT0();
        }
        __syncthreads();

        // ---- mma partial: [128 gates] x [32 b] over k-slice ----
        float acc[4][4];
#pragma unroll
        for (int nt = 0; nt < 4; nt++)
#pragma unroll
            for (int r = 0; r < 4; r++) acc[nt][r] = 0.0f;

#pragma unroll
        for (int k8 = 0; k8 < 16; k8++) {
            int kk = (k8 << 3) + t4;
            int r0 = (rowbase + gid) * 132 + kk;
            int r1 = r0 + 8 * 132;
            unsigned ah[4], al[4];
            ah[0] = __float_as_uint(Wh[r0]);
            ah[1] = __float_as_uint(Wh[r1]);
            ah[2] = __float_as_uint(Wh[r0 + 4]);
            ah[3] = __float_as_uint(Wh[r1 + 4]);
            al[0] = __float_as_uint(Wl[r0]);
            al[1] = __float_as_uint(Wl[r1]);
            al[2] = __float_as_uint(Wl[r0 + 4]);
            al[3] = __float_as_uint(Wl[r1 + 4]);
#pragma unroll
            for (int nt = 0; nt < 4; nt++) {
                int ci = ((nt << 3) + gid) * 132 + kk;
                unsigned bh[2], bl[2];
                bh[0] = __float_as_uint(Hh[ci]);
                bh[1] = __float_as_uint(Hh[ci + 4]);
                bl[0] = __float_as_uint(Hl[ci]);
                bl[1] = __float_as_uint(Hl[ci + 4]);
                MMA_TF32(acc[nt], ah, bh);
                MMA_TF32(acc[nt], ah, bl);
                MMA_TF32(acc[nt], al, bh);
            }
        }

        // ---- store partials ----
        {
            size_t pbase = ((size_t)(d * 4 + ks) * NG + g0) * NB;
            int grow = rowbase + gid;
#pragma unroll
            for (int nt = 0; nt < 4; nt++) {
                int b = (nt << 3) + (t4 << 1);
                float2 p0 = {acc[nt][0], acc[nt][1]};
                float2 p1 = {acc[nt][2], acc[nt][3]};
                *(float2*)&g_part[pbase + (size_t)grow * NB + b] = p0;
                *(float2*)&g_part[pbase + (size_t)(grow + 8) * NB + b] = p1;
            }
        }
        __threadfence();
        gridbar();

        // ---- combine: one (b, j) per thread ----
        {
            float gate[4];
            const float* gxr = gx + ((size_t)d * NTOK + (size_t)cb * NL + t) * NG;
#pragma unroll
            for (int gi = 0; gi < 4; gi++) {
                int g = gi * NH + cj;
                float v = __ldg(&gxr[g]);
#pragma unroll
                for (int kss = 0; kss < 4; kss++)
                    v += __ldcg(&g_part[((size_t)(d * 4 + kss) * NG + g) * NB + cb]);
                gate[gi] = v;
            }
            float cn = sigf(gate[1]) * creg + sigf(gate[0]) * tanhf_fast(gate[2]);
            float hn = sigf(gate[3]) * tanhf_fast(cn);
            float mt = mask[cb * NL + t];
            hreg = hreg + (hn - hreg) * mt;
            creg = creg + (cn - creg) * mt;
            out[((size_t)cb * NL + t) * 1024 + (d << 9) + cj] = hreg;
            float hh, hl;
            tf32split(hreg, hh, hl);
            size_t hidx = (size_t)(d * NB + cb) * NH + cj;
            g_hph[hidx] = hh;
            g_hpl[hidx] = hl;
        }
        __threadfence();
        gridbar();
    }
}

// ------------------ per-token combine ------------------
__global__ __launch_bounds__(256) void k_comb(const float* __restrict__ w2,
                                              const float* __restrict__ b2,
                                              const int* __restrict__ tgt,
                                              const float* __restrict__ cew,
                                              float* __restrict__ dout) {
    int warp = threadIdx.x >> 5, lane = threadIdx.x & 31;
    int m = blockIdx.x * 8 + warp;

    float lm = -1e30f, ls = 0.0f;
    int la = 0;
    for (int vt = lane; vt < NVT; vt += 32) {
        float tmx = g_pmax[(size_t)m * NVT + vt];
        float tsm = g_psum[(size_t)m * NVT + vt];
        int tag = g_parg[(size_t)m * NVT + vt];
        if (tmx > lm) {
            ls = ls * __expf(lm - tmx) + tsm;
            lm = tmx;
            la = tag;
        } else {
            ls += tsm * __expf(tmx - lm);
        }
    }
#pragma unroll
    for (int off = 16; off; off >>= 1) {
        float om = __shfl_down_sync(0xffffffffu, lm, off);
        float os = __shfl_down_sync(0xffffffffu, ls, off);
        int oa = __shfl_down_sync(0xffffffffu, la, off);
        float nm = fmaxf(lm, om);
        float ns = ls * __expf(lm - nm) + os * __expf(om - nm);
        int na = (om > lm) ? oa : ((om == lm && oa < la) ? oa : la);
        lm = nm; ls = ns; la = na;
    }

    int tg = tgt[m];
    float4 hv = *(const float4*)&g_hid[(size_t)m * 128 + lane * 4];
    float4 wv = *(const float4*)&w2[(size_t)tg * 128 + lane * 4];
    float dp = hv.x * wv.x + hv.y * wv.y + hv.z * wv.z + hv.w * wv.w;
#pragma unroll
    for (int off = 16; off; off >>= 1) dp += __shfl_down_sync(0xffffffffu, dp, off);

    if (lane == 0) {
        float logit_t = dp + b2[tg];
        float lse = lm + logf(ls);
        float nll = lse - logit_t;
        float w = cew[tg];
        g_nllw[m] = nll * w;
        g_wtok[m] = w;
        dout[1 + m] = (float)la;
    }
}

// ------------------ final loss reduce ------------------
__global__ __launch_bounds__(256) void k_loss(float* __restrict__ dout) {
    __shared__ float s1[256];
    __shared__ float s2[256];
    int tid = threadIdx.x;
    float a = 0.0f, b = 0.0f;
    for (int i = tid; i < NTOK; i += 256) { a += g_nllw[i]; b += g_wtok[i]; }
    s1[tid] = a; s2[tid] = b;
    __syncthreads();
    for (int off = 128; off; off >>= 1) {
        if (tid < off) { s1[tid] += s1[tid + off]; s2[tid] += s2[tid + off]; }
        __syncthreads();
    }
    if (tid == 0) dout[0] = s1[0] / s2[0];
}

// ------------------ launch ------------------
extern "C" void kernel_launch(void* const* d_in, const int* in_sizes, int n_in,
                              void* d_out, int out_size) {
    const int* inp_word = (const int*)d_in[0];
    const float* inp_mask = (const float*)d_in[1];
    const int* tgt_word = (const int*)d_in[3];
    const float* emb = (const float*)d_in[4];
    const float* w_ih0 = (const float*)d_in[5];
    const float* w_hh0 = (const float*)d_in[6];
    const float* b0 = (const float*)d_in[7];
    const float* w_ih = (const float*)d_in[8];
    const float* w_hh = (const float*)d_in[9];
    const float* bb = (const float*)d_in[10];
    const float* dec_w1 = (const float*)d_in[11];
    const float* dec_b1 = (const float*)d_in[12];
    const float* dec_w2 = (const float*)d_in[13];
    const float* dec_b2 = (const float*)d_in[14];
    const float* cew = (const float*)d_in[15];
    float* out = (float*)d_out;

    float *pgx, *pA, *pB, *phid, *pwh, *pwl, *pah, *pal, *pwhh, *pwhl;
    cudaGetSymbolAddress((void**)&pgx, g_gx);
    cudaGetSymbolAddress((void**)&pA, g_bufA);
    cudaGetSymbolAddress((void**)&pB, g_bufB);
    cudaGetSymbolAddress((void**)&phid, g_hid);
    cudaGetSymbolAddress((void**)&pwh, g_wh);
    cudaGetSymbolAddress((void**)&pwl, g_wl);
    cudaGetSymbolAddress((void**)&pah, g_ah);
    cudaGetSymbolAddress((void**)&pal, g_al);
    cudaGetSymbolAddress((void**)&pwhh, g_whhh);
    cudaGetSymbolAddress((void**)&pwhl, g_whhl);

    const int gsm = 2 * STAGE * 4;                 // 81920 bytes
    const int ssm = (2 * 16896 + 2 * 4224) * 4;    // 168960 bytes
    cudaFuncSetAttribute(k_gemm2, cudaFuncAttributeMaxDynamicSharedMemorySize, gsm);
    cudaFuncSetAttribute(k_dec2m, cudaFuncAttributeMaxDynamicSharedMemorySize, gsm);
    cudaFuncSetAttribute(k_scan4, cudaFuncAttributeMaxDynamicSharedMemorySize, ssm);

    // 0. split all weights into tf32 hi/lo planes
    k_split<<<512, 256>>>(w_ih0, pwh + OFF_WIH0, pwl + OFF_WIH0, 524288 / 4);
    k_split<<<8192, 256>>>(w_ih, pwh + OFF_WIH1, pwl + OFF_WIH1, 8388608 / 4);
    k_split<<<128, 256>>>(dec_w1, pwh + OFF_W1, pwl + OFF_W1, 131072 / 4);
    k_split<<<4000, 256>>>(dec_w2, pwh + OFF_W2, pwl + OFF_W2, 4096000 / 4);
    k_split<<<2048, 256>>>(w_hh0, pwhh, pwhl, 2097152 / 4);
    k_split<<<4096, 256>>>(w_hh, pwhh + 2097152, pwhl + 2097152, 4194304 / 4);

    // 1. embedding (split planes, K=128)
    k_embed<<<(NTOK * NE) / 256, 256>>>(inp_word, emb);

    // 2. layer 0
    k_gemm2<<<dim3(NG / 128, NTOK / 128, 2), 256, gsm>>>(
        pah, pal, pwh + OFF_WIH0, pwl + OFF_WIH0, b0, pgx,
        NE, NG, (long long)NG * NE, NG, (long long)NTOK * NG, 0);
    k_zero<<<128, 256>>>();
    k_scan4<<<128, 256, ssm>>>(pgx, inp_mask, pA, pwhh, pwhl);

    // 3. layer 1
    k_split<<<4096, 256>>>(pA, pah, pal, (NTOK * 1024) / 4);
    k_gemm2<<<dim3(NG / 128, NTOK / 128, 2), 256, gsm>>>(
        pah, pal, pwh + OFF_WIH1, pwl + OFF_WIH1, bb, pgx,
        1024, NG, (long long)NG * 1024, NG, (long long)NTOK * NG, 0);
    k_zero<<<128, 256>>>();
    k_scan4<<<128, 256, ssm>>>(pgx, inp_mask, pB, pwhh + 2097152, pwhl + 2097152);

    // 4. layer 2
    k_split<<<4096, 256>>>(pB, pah, pal, (NTOK * 1024) / 4);
    k_gemm2<<<dim3(NG / 128, NTOK / 128, 2), 256, gsm>>>(
        pah, pal, pwh + OFF_WIH1 + 4194304, pwl + OFF_WIH1 + 4194304,
        bb + 2 * NG, pgx,
        1024, NG, (long long)NG * 1024, NG, (long long)NTOK * NG, 0);
    k_zero<<<128, 256>>>();
    k_scan4<<<128, 256, ssm>>>(pgx, inp_mask, pA, pwhh + 4194304, pwhl + 4194304);

    // 5. decoder layer 1 (relu, writes g_hid + split planes)
    k_split<<<4096, 256>>>(pA, pah, pal, (NTOK * 1024) / 4);
    k_gemm2<<<dim3(1, NTOK / 128, 1), 256, gsm>>>(
        pah, pal, pwh + OFF_W1, pwl + OFF_W1, dec_b1, phid,
        1024, 128, 0, 0, 0, 2);

    // 6. decoder layer 2 (mma) + fused online softmax partials
    k_dec2m<<<dim3(NVT, NTOK / 128), 256, gsm>>>(dec_b2);

    // 7. per-token combine
    k_comb<<<NTOK / 8, 256>>>(dec_w2, dec_b2, tgt_word, cew, out);

    // 8. loss reduce
    k_loss<<<1, 256>>>(out);
}